// round 7
// baseline (speedup 1.0000x reference)
#include <cuda_runtime.h>
#include <math.h>

// ModifiedChamferLoss: H=W=M=512, N=H*W=262144
// d_in[0]=prob_map [262144] f32, d_in[1]=gt [512,2] f32 (d_in[2] unused; coords from index)
// out: scalar f32

#define NPIX  262144
#define MPTS  512
#define NB2   512                 /* term2 blocks: one image row each        */
#define NB1   256                 /* term1 blocks: one 32x32 pixel tile each */
#define NBTOT (NB1 + NB2)
#define TPB   512
#define FULLM 0xffffffffu

#define EPSF        1e-6f
#define MAXD_F      724.07733f          /* sqrt(512^2+512^2) */
#define MAXD2_F     524288.0f
#define EPS_OVER_MD 1.3810683e-9f       /* 1e-6f / 724.07733f */

typedef unsigned long long ull;

__device__ __forceinline__ ull pk2(float lo, float hi) {
    ull r; asm("mov.b64 %0, {%1, %2};" : "=l"(r) : "f"(lo), "f"(hi)); return r;
}
#define UNPK2(a, b, v) asm("mov.b64 {%0, %1}, %2;" : "=f"(a), "=f"(b) : "l"(v))
__device__ __forceinline__ ull add2(ull a, ull b) {
    ull r; asm("add.rn.f32x2 %0, %1, %2;" : "=l"(r) : "l"(a), "l"(b)); return r;
}
__device__ __forceinline__ ull mul2(ull a, ull b) {
    ull r; asm("mul.rn.f32x2 %0, %1, %2;" : "=l"(r) : "l"(a), "l"(b)); return r;
}
__device__ __forceinline__ ull fma2(ull a, ull b, ull c) {
    ull r; asm("fma.rn.f32x2 %0, %1, %2, %3;" : "=l"(r) : "l"(a), "l"(b), "l"(c)); return r;
}

__device__ float    g_sum_pd;      // sum p * min_j d
__device__ float    g_sum_p;       // sum p
__device__ int      g_min2[MPTS];  // per-GT min candidate^2, ORIGINAL gt order (float bits)
__device__ float    g_sgy[MPTS];   // gt y, sorted by gx ascending
__device__ float    g_sgx[MPTS];   // gt x, sorted ascending
__device__ int      g_sidx[MPTS];  // sorted position -> original index
__device__ unsigned g_done;        // block completion ticket

// prep (32 blocks): blocks 0-15 rank-sort GT by x (16 thr/GT); blocks 16-31 seed
// g_min2 with exact candidates from 64 pixels near each GT (16 thr/GT x 4 px).
__global__ void __launch_bounds__(TPB)
chamfer_prep(const float* __restrict__ prob, const float* __restrict__ gt)
{
    const int b = blockIdx.x;
    const int t = threadIdx.x;

    if (b < 16) {
        __shared__ float sgx[MPTS], sgy[MPTS];
        __shared__ int   srank[32];
        {
            float2 g = ((const float2*)gt)[t];
            sgy[t] = g.x; sgx[t] = g.y;
        }
        if (t < 32) srank[t] = 0;
        if (b == 0 && t == 0) { g_sum_pd = 0.0f; g_sum_p = 0.0f; g_done = 0u; }
        __syncthreads();

        const int   j  = (b << 5) + (t >> 4);     // this block's 32 GT points
        const float gx = sgx[j];
        const int   k0 = (t & 15) << 5;           // 16 threads cover 512 in 32-slices
        int cnt = 0;
        #pragma unroll 8
        for (int k = k0; k < k0 + 32; ++k) {
            float o = sgx[k];
            cnt += (o < gx) || (o == gx && k < j);
        }
        atomicAdd(&srank[t >> 4], cnt);
        __syncthreads();
        if ((t & 15) == 0) {
            int r = srank[t >> 4];
            g_sgy[r]  = sgy[j];
            g_sgx[r]  = sgx[j];
            g_sidx[r] = j;
        }
    } else {
        // seed: GT j scanned by 16 threads x 4 pixels in its nearest row, gx +/- 32
        const int j = ((b - 16) << 5) + (t >> 4);
        float2 g = ((const float2*)gt)[j];
        const float gy = g.x, gx = g.y;
        const int row = min(max(__float2int_rn(gy), 0), 511);
        const int cb  = min(max(__float2int_rn(gx) - 32, 0), 448);
        const int c0  = cb + ((t & 15) << 2);
        const float dy  = (float)row - gy;
        const float dy2 = dy * dy;

        float best = MAXD2_F;
        #pragma unroll
        for (int u = 0; u < 4; ++u) {
            int   c  = c0 + u;
            float p  = prob[row * 512 + c];
            float p2 = p * p;
            float s  = 1.0f / (p2 * p2 + EPS_OVER_MD);
            float dx = (float)c - gx;
            float d2 = fmaf(dx, dx, dy2);
            float cand = fminf((sqrtf(d2) + EPSF) * s, MAXD_F);
            best = fminf(best, cand * cand);
        }
        #pragma unroll
        for (int o = 8; o; o >>= 1)
            best = fminf(best, __shfl_down_sync(FULLM, best, o, 16));
        if ((t & 15) == 0) g_min2[j] = __float_as_int(best);
    }
}

__global__ void __launch_bounds__(TPB)
chamfer_main(const float* __restrict__ prob, const float* __restrict__ gt,
             float* __restrict__ out)
{
    const int tid  = threadIdx.x;
    const int lane = tid & 31;
    const int wid  = tid >> 5;
    __shared__ unsigned s_last;

    if (blockIdx.x < NB2) {
        // ========== term2: block = one image row; thread = one GT column ==========
        __shared__ __align__(16) float ss[TPB];    // s  = 1/(p^4+eps')
        __shared__ __align__(16) float ss2[TPB];   // s^2
        __shared__ float s_c2min[TPB / 8];         // per-8px-chunk min of s^2
        __shared__ float s_rowmin;                 // row min of s^2

        const int row = blockIdx.x;
        {
            float p  = prob[row * 512 + tid];
            float p2 = p * p;
            float s  = 1.0f / (p2 * p2 + EPS_OVER_MD);
            ss[tid]  = s;
            ss2[tid] = s * s;
        }
        __syncthreads();
        if (tid < 64) {
            float m = ss2[tid * 8];
            #pragma unroll
            for (int u = 1; u < 8; ++u) m = fminf(m, ss2[tid * 8 + u]);
            s_c2min[tid] = m;
        }
        __syncthreads();
        if (tid < 32) {
            float m = fminf(s_c2min[tid], s_c2min[tid + 32]);
            #pragma unroll
            for (int o = 16; o; o >>= 1) m = fminf(m, __shfl_down_sync(FULLM, m, o));
            if (tid == 0) s_rowmin = m;
        }
        __syncthreads();

        const float gy  = g_sgy[tid];
        const float gx  = g_sgx[tid];
        const int   idx = g_sidx[tid];              // original index for g_min2
        const float dy  = (float)row - gy;
        const float dy2 = dy * dy;

        // warp-uniform wrap-around start — MUST be computed at full warp activity
        // (hoisted out of the divergent branch: shfl_sync inside it deadlocks when
        //  the non-participating lanes sit at the final __syncthreads()).
        const int start = __float2int_rz(__shfl_sync(FULLM, gx, 0)) >> 3;

        const float seed  = __int_as_float(*((volatile int*)&g_min2[idx]));
        float       cmin2 = seed;

        // row-level lower bound: all candidates in this row have cand^2 >= dy2*s2min_row
        if (dy2 * s_rowmin < cmin2) {
            const ull dy2v = pk2(dy2, dy2);
            const ull two2 = pk2(2.0f, 2.0f);

            for (int cc = 0; cc < 64; ++cc) {
                int   c    = (start + cc) & 63;
                float xm   = (float)(c << 3) - gx;                       // x0 - gx
                float dxlb = fmaxf(fmaxf(-xm - 7.0f, xm), 0.0f);
                float d2lb = fmaf(dxlb, dxlb, dy2);
                if (d2lb * s_c2min[c] < cmin2) {
                    ull   dxv  = pk2(xm, xm + 1.0f);
                    float tmin = 3.4e38f;
                    #pragma unroll
                    for (int u = 0; u < 8; u += 2) {
                        ull s2v = *(const ull*)&ss2[(c << 3) + u];
                        ull d2v = fma2(dxv, dxv, dy2v);
                        ull tv  = mul2(d2v, s2v);
                        float t0, t1; UNPK2(t0, t1, tv);
                        tmin = fminf(tmin, fminf(t0, t1));
                        dxv  = add2(dxv, two2);
                    }
                    // t = d2*s2 <= cand^2, so tmin >= cmin2 proves no win in chunk
                    if (tmin < cmin2) {
                        #pragma unroll
                        for (int u = 0; u < 8; ++u) {
                            int   k  = (c << 3) + u;
                            float dx = (float)k - gx;
                            float d2 = fmaf(dx, dx, dy2);
                            if (d2 * ss2[k] < cmin2) {
                                float cand = fminf((sqrtf(d2) + EPSF) * ss[k], MAXD_F);
                                cmin2 = fminf(cmin2, cand * cand);
                            }
                        }
                    }
                }
                if ((cc & 15) == 15)  // refresh from global running min
                    cmin2 = fminf(cmin2, __int_as_float(*((volatile int*)&g_min2[idx])));
            }
        }
        if (cmin2 < seed)
            atomicMin(&g_min2[idx], __float_as_int(cmin2));
    } else {
        // ========== term1: block = 32x32 pixel tile; GT candidates pruned by triangle ineq ==========
        __shared__ __align__(16) float s_cgy[MPTS + 2];   // negated, compacted
        __shared__ __align__(16) float s_cgx[MPTS + 2];
        __shared__ float s_wred[16];
        __shared__ int   s_wcnt[16];
        __shared__ float r_pd[TPB / 32], r_p[TPB / 32];

        const int b1  = blockIdx.x - NB2;
        const int ty0 = (b1 >> 4) << 5;
        const int tx0 = (b1 & 15) << 5;
        const float cy = (float)ty0 + 15.5f, cx = (float)tx0 + 15.5f;

        // phase A: candidate selection. keep g iff d(c,g) <= dmin_c + 2*r_tile (+slack)
        float2 g   = ((const float2*)gt)[tid];
        float  dyc = cy - g.x, dxc = cx - g.y;
        float  dc  = sqrtf(fmaf(dyc, dyc, dxc * dxc));

        float m = dc;
        #pragma unroll
        for (int o = 16; o; o >>= 1) m = fminf(m, __shfl_down_sync(FULLM, m, o));
        if (lane == 0) s_wred[wid] = m;
        __syncthreads();
        float dmin = s_wred[0];
        #pragma unroll
        for (int w = 1; w < 16; ++w) dmin = fminf(dmin, s_wred[w]);

        bool     keep = dc <= dmin + 44.3407f;   // 2*21.9203 (tile radius) + 0.5 slack
        unsigned bal  = __ballot_sync(FULLM, keep);
        if (lane == 0) s_wcnt[wid] = __popc(bal);
        __syncthreads();
        int base = 0, ncand = 0;
        #pragma unroll
        for (int w = 0; w < 16; ++w) { int cw = s_wcnt[w]; ncand += cw; if (w < wid) base += cw; }
        if (keep) {
            int pos = base + __popc(bal & ((1u << lane) - 1u));
            s_cgy[pos] = -g.x;
            s_cgx[pos] = -g.y;
        }
        __syncthreads();
        if (tid == 0 && (ncand & 1)) { s_cgy[ncand] = s_cgy[ncand - 1]; s_cgx[ncand] = s_cgx[ncand - 1]; }
        const int np = (ncand + 1) & ~1;
        __syncthreads();

        // phase B: 2 vertically-aligned pixels per thread (shared dx^2), 2 candidates per step
        const int y0i = ty0 + (tid >> 5), x0i = tx0 + (tid & 31);
        const int i0  = y0i * 512 + x0i;
        const int i1  = i0 + 16 * 512;
        const float p0 = prob[i0], p1 = prob[i1];

        const ull yy0 = pk2((float)y0i, (float)y0i);
        const ull yy1 = pk2((float)(y0i + 16), (float)(y0i + 16));
        const ull xx0 = pk2((float)x0i, (float)x0i);

        float ma0 = 3.4e38f, mb0 = 3.4e38f, ma1 = 3.4e38f, mb1 = 3.4e38f;
        #pragma unroll 2
        for (int j = 0; j < np; j += 2) {
            ull gyv = *(const ull*)&s_cgy[j];
            ull gxv = *(const ull*)&s_cgx[j];
            ull dxv = add2(gxv, xx0);
            ull dxx = mul2(dxv, dxv);
            {
                ull dyv = add2(gyv, yy0);
                ull d2  = fma2(dyv, dyv, dxx);
                float a, b; UNPK2(a, b, d2);
                ma0 = fminf(ma0, a); mb0 = fminf(mb0, b);
            }
            {
                ull dyv = add2(gyv, yy1);
                ull d2  = fma2(dyv, dyv, dxx);
                float a, b; UNPK2(a, b, d2);
                ma1 = fminf(ma1, a); mb1 = fminf(mb1, b);
            }
        }

        float v_pd = p0 * sqrtf(fminf(ma0, mb0)) + p1 * sqrtf(fminf(ma1, mb1));
        float v_p  = p0 + p1;
        #pragma unroll
        for (int o = 16; o; o >>= 1) {
            v_pd += __shfl_down_sync(FULLM, v_pd, o);
            v_p  += __shfl_down_sync(FULLM, v_p,  o);
        }
        if (lane == 0) { r_pd[wid] = v_pd; r_p[wid] = v_p; }
        __syncthreads();
        if (tid == 0) {
            float a = 0.0f, b = 0.0f;
            #pragma unroll
            for (int w = 0; w < TPB / 32; ++w) { a += r_pd[w]; b += r_p[w]; }
            atomicAdd(&g_sum_pd, a);
            atomicAdd(&g_sum_p,  b);
        }
    }

    // ========== fused finalize: last block to finish reduces and writes out ==========
    __syncthreads();                     // all this block's global atomics issued
    if (tid == 0) {
        __threadfence();                 // make them visible before the ticket
        unsigned old = atomicAdd(&g_done, 1u);
        s_last = (old == NBTOT - 1u) ? 1u : 0u;
    }
    __syncthreads();
    if (s_last) {
        __threadfence();                 // acquire: see all other blocks' writes
        float cand = sqrtf(__int_as_float(*((volatile int*)&g_min2[tid])));
        #pragma unroll
        for (int o = 16; o; o >>= 1)
            cand += __shfl_down_sync(FULLM, cand, o);
        __shared__ float rfin[TPB / 32];
        if (lane == 0) rfin[wid] = cand;
        __syncthreads();
        if (tid == 0) {
            float t2 = 0.0f;
            #pragma unroll
            for (int w = 0; w < TPB / 32; ++w) t2 += rfin[w];
            t2 *= (1.0f / (float)MPTS);
            float spd = *((volatile float*)&g_sum_pd);
            float sp  = *((volatile float*)&g_sum_p);
            out[0] = spd / (sp + EPSF) + t2;
        }
    }
}

extern "C" void kernel_launch(void* const* d_in, const int* in_sizes, int n_in,
                              void* d_out, int out_size)
{
    const float* prob = (const float*)d_in[0];
    const float* gt   = (const float*)d_in[1];
    (void)in_sizes; (void)n_in; (void)out_size;

    chamfer_prep<<<32, TPB>>>(prob, gt);
    chamfer_main<<<NBTOT, TPB>>>(prob, gt, (float*)d_out);
}

// round 8
// speedup vs baseline: 2.2904x; 2.2904x over previous
#include <cuda_runtime.h>
#include <math.h>

// ModifiedChamferLoss: H=W=M=512, N=H*W=262144
// d_in[0]=prob_map [262144] f32, d_in[1]=gt [512,2] f32 (d_in[2] unused; coords from index)
// out: scalar f32
//
// Single launch. term1: 256 blocks of 32x32 pixel tiles (triangle-inequality GT pruning).
// term2: 32 blocks x 16 warps, one GT per warp. Since s=1/(p^4+eps') >= ~1, any achieved
// upper bound U on the per-GT min restricts winners to distance <= U*(1+eps'), so a 32x32
// box scan + coverage check is exact (with square-expansion fallback). Last block (u64
// modular ticket -> replay-safe without init) reduces partials and writes the scalar.

#define MPTS  512
#define NB1   256                 /* term1 tile blocks            */
#define NB2B  32                  /* term2 blocks (16 warps each) */
#define NBTOT (NB1 + NB2B)
#define TPB   512
#define FULLM 0xffffffffu

#define EPSF        1e-6f
#define MAXD_F      724.07733f          /* sqrt(512^2+512^2) */
#define MAXD2_F     524288.0f
#define EPS_OVER_MD 1.3810683e-9f       /* 1e-6f / 724.07733f */

typedef unsigned long long ull;

__device__ __forceinline__ ull pk2(float lo, float hi) {
    ull r; asm("mov.b64 %0, {%1, %2};" : "=l"(r) : "f"(lo), "f"(hi)); return r;
}
#define UNPK2(a, b, v) asm("mov.b64 {%0, %1}, %2;" : "=f"(a), "=f"(b) : "l"(v))
__device__ __forceinline__ ull add2(ull a, ull b) {
    ull r; asm("add.rn.f32x2 %0, %1, %2;" : "=l"(r) : "l"(a), "l"(b)); return r;
}
__device__ __forceinline__ ull mul2(ull a, ull b) {
    ull r; asm("mul.rn.f32x2 %0, %1, %2;" : "=l"(r) : "l"(a), "l"(b)); return r;
}
__device__ __forceinline__ ull fma2(ull a, ull b, ull c) {
    ull r; asm("fma.rn.f32x2 %0, %1, %2, %3;" : "=l"(r) : "l"(a), "l"(b), "l"(c)); return r;
}

__device__ float g_part_pd[NB1];   // per-term1-block partial: sum p*min_d
__device__ float g_part_p[NB1];    // per-term1-block partial: sum p
__device__ int   g_min2[MPTS];     // per-GT min candidate^2 (float bits), plain stores
__device__ ull   g_done;           // persistent ticket; last block of each launch via mod

__global__ void __launch_bounds__(TPB)
chamfer_all(const float* __restrict__ prob, const float* __restrict__ gt,
            float* __restrict__ out)
{
    const int tid  = threadIdx.x;
    const int lane = tid & 31;
    const int wid  = tid >> 5;
    __shared__ unsigned s_last;

    if (blockIdx.x < NB1) {
        // ========== term1: block = 32x32 pixel tile; GT candidates pruned by triangle ineq ==========
        __shared__ __align__(16) float s_cgy[MPTS + 2];   // negated, compacted
        __shared__ __align__(16) float s_cgx[MPTS + 2];
        __shared__ float s_wred[16];
        __shared__ int   s_wcnt[16];
        __shared__ float r_pd[TPB / 32], r_p[TPB / 32];

        const int b1  = blockIdx.x;
        const int ty0 = (b1 >> 4) << 5;
        const int tx0 = (b1 & 15) << 5;
        const float cy = (float)ty0 + 15.5f, cx = (float)tx0 + 15.5f;

        // phase A: keep GT g iff d(center,g) <= dmin_center + 2*r_tile (+slack)
        float2 g   = ((const float2*)gt)[tid];
        float  dyc = cy - g.x, dxc = cx - g.y;
        float  dc  = sqrtf(fmaf(dyc, dyc, dxc * dxc));

        float m = dc;
        #pragma unroll
        for (int o = 16; o; o >>= 1) m = fminf(m, __shfl_down_sync(FULLM, m, o));
        if (lane == 0) s_wred[wid] = m;
        __syncthreads();
        float dmin = s_wred[0];
        #pragma unroll
        for (int w = 1; w < 16; ++w) dmin = fminf(dmin, s_wred[w]);

        bool     keep = dc <= dmin + 44.3407f;   // 2*21.9203 (tile radius) + 0.5 slack
        unsigned bal  = __ballot_sync(FULLM, keep);
        if (lane == 0) s_wcnt[wid] = __popc(bal);
        __syncthreads();
        int base = 0, ncand = 0;
        #pragma unroll
        for (int w = 0; w < 16; ++w) { int cw = s_wcnt[w]; ncand += cw; if (w < wid) base += cw; }
        if (keep) {
            int pos = base + __popc(bal & ((1u << lane) - 1u));
            s_cgy[pos] = -g.x;
            s_cgx[pos] = -g.y;
        }
        __syncthreads();
        if (tid == 0 && (ncand & 1)) { s_cgy[ncand] = s_cgy[ncand - 1]; s_cgx[ncand] = s_cgx[ncand - 1]; }
        const int np = (ncand + 1) & ~1;
        __syncthreads();

        // phase B: 2 vertically-aligned pixels per thread (shared dx^2), 2 candidates per step
        const int y0i = ty0 + (tid >> 5), x0i = tx0 + (tid & 31);
        const int i0  = y0i * 512 + x0i;
        const int i1  = i0 + 16 * 512;
        const float p0 = prob[i0], p1 = prob[i1];

        const ull yy0 = pk2((float)y0i, (float)y0i);
        const ull yy1 = pk2((float)(y0i + 16), (float)(y0i + 16));
        const ull xx0 = pk2((float)x0i, (float)x0i);

        float ma0 = 3.4e38f, mb0 = 3.4e38f, ma1 = 3.4e38f, mb1 = 3.4e38f;
        #pragma unroll 2
        for (int j = 0; j < np; j += 2) {
            ull gyv = *(const ull*)&s_cgy[j];
            ull gxv = *(const ull*)&s_cgx[j];
            ull dxv = add2(gxv, xx0);
            ull dxx = mul2(dxv, dxv);
            {
                ull dyv = add2(gyv, yy0);
                ull d2  = fma2(dyv, dyv, dxx);
                float a, b; UNPK2(a, b, d2);
                ma0 = fminf(ma0, a); mb0 = fminf(mb0, b);
            }
            {
                ull dyv = add2(gyv, yy1);
                ull d2  = fma2(dyv, dyv, dxx);
                float a, b; UNPK2(a, b, d2);
                ma1 = fminf(ma1, a); mb1 = fminf(mb1, b);
            }
        }

        float v_pd = p0 * sqrtf(fminf(ma0, mb0)) + p1 * sqrtf(fminf(ma1, mb1));
        float v_p  = p0 + p1;
        #pragma unroll
        for (int o = 16; o; o >>= 1) {
            v_pd += __shfl_down_sync(FULLM, v_pd, o);
            v_p  += __shfl_down_sync(FULLM, v_p,  o);
        }
        if (lane == 0) { r_pd[wid] = v_pd; r_p[wid] = v_p; }
        __syncthreads();
        if (tid == 0) {
            float a = 0.0f, b = 0.0f;
            #pragma unroll
            for (int w = 0; w < TPB / 32; ++w) { a += r_pd[w]; b += r_p[w]; }
            g_part_pd[b1] = a;      // plain stores (no init needed)
            g_part_p[b1]  = b;
        }
    } else {
        // ========== term2: one GT point per warp ==========
        const int j  = ((blockIdx.x - NB1) << 4) + wid;    // 0..511
        const float gy = __ldg(&gt[2 * j]);
        const float gx = __ldg(&gt[2 * j + 1]);
        const int ry = min(max(__float2int_rn(gy), 0), 511);
        const int rx = min(max(__float2int_rn(gx), 0), 511);
        const int r0 = min(max(ry - 15, 0), 480);          // 32-row box
        const int c0 = min(max(rx - 15, 0), 480);          // 32-col box

        // seed scan: 32x32 box, lane owns one column, coalesced row loads
        const int   col = c0 + lane;
        const float dxl = (float)col - gx;
        const float dx2 = dxl * dxl;
        float cmin2 = MAXD2_F;
        #pragma unroll 4
        for (int r = r0; r < r0 + 32; ++r) {
            float p   = __ldg(&prob[r * 512 + col]);
            float dyl = (float)r - gy;
            float d2  = fmaf(dyl, dyl, dx2);
            float p2  = p * p;
            float s   = 1.0f / (p2 * p2 + EPS_OVER_MD);
            float cand = fminf((sqrtf(d2) + EPSF) * s, MAXD_F);
            cmin2 = fminf(cmin2, cand * cand);
        }
        cmin2 = __uint_as_float(__reduce_min_sync(FULLM, __float_as_uint(cmin2)));

        // coverage radius of the box around (gy,gx); image-edge sides cover everything
        float top = (r0 > 0)        ? (gy - (float)r0)          : 1e9f;
        float bot = (r0 + 31 < 511) ? ((float)(r0 + 31) - gy)   : 1e9f;
        float lef = (c0 > 0)        ? (gx - (float)c0)          : 1e9f;
        float rig = (c0 + 31 < 511) ? ((float)(c0 + 31) - gx)   : 1e9f;
        float rcov = fminf(fminf(top, bot), fminf(lef, rig));

        // every cand >= d/(1+eps'), so pixels with d > U*(1+eps') cannot win.
        // If U (=sqrt(cmin2)) <= rcov (with margin), the box scan was exhaustive.
        if (cmin2 > rcov * rcov * 0.98f) {   // exact fallback (statistically never)
            int W   = (int)ceilf(sqrtf(cmin2) * 1.001f) + 1;
            int rr0 = max(0, ry - W), rr1 = min(511, ry + W);
            int cc0 = max(0, rx - W), cc1 = min(511, rx + W);
            for (int r = rr0; r <= rr1; ++r) {
                float dyl = (float)r - gy;
                float dy2 = dyl * dyl;
                for (int c = cc0 + lane; c <= cc1; c += 32) {
                    float p   = prob[r * 512 + c];
                    float dxe = (float)c - gx;
                    float d2  = fmaf(dxe, dxe, dy2);
                    float p2  = p * p;
                    float s   = 1.0f / (p2 * p2 + EPS_OVER_MD);
                    float cand = fminf((sqrtf(d2) + EPSF) * s, MAXD_F);
                    cmin2 = fminf(cmin2, cand * cand);
                }
            }
            cmin2 = __uint_as_float(__reduce_min_sync(FULLM, __float_as_uint(cmin2)));
        }
        if (lane == 0) g_min2[j] = __float_as_int(cmin2);   // plain store
    }

    // ========== fused finalize: last block of THIS launch reduces and writes out ==========
    __syncthreads();                       // all block results stored
    if (tid == 0) {
        __threadfence();                   // publish stores before the ticket
        ull old = atomicAdd(&g_done, 1ull);
        s_last = ((old % (ull)NBTOT) == (ull)(NBTOT - 1)) ? 1u : 0u;
    }
    __syncthreads();
    if (s_last) {
        __threadfence();                   // acquire all other blocks' stores
        float v0 = sqrtf(__int_as_float(((volatile int*)g_min2)[tid]));          // term2
        float v1 = (tid < NB1) ? ((volatile float*)g_part_pd)[tid] : 0.0f;       // term1 pd
        float v2 = (tid < NB1) ? ((volatile float*)g_part_p)[tid]  : 0.0f;       // term1 p
        #pragma unroll
        for (int o = 16; o; o >>= 1) {
            v0 += __shfl_down_sync(FULLM, v0, o);
            v1 += __shfl_down_sync(FULLM, v1, o);
            v2 += __shfl_down_sync(FULLM, v2, o);
        }
        __shared__ float rf0[16], rf1[16], rf2[16];
        if (lane == 0) { rf0[wid] = v0; rf1[wid] = v1; rf2[wid] = v2; }
        __syncthreads();
        if (tid == 0) {
            float t2 = 0.0f, spd = 0.0f, sp = 0.0f;
            #pragma unroll
            for (int w = 0; w < 16; ++w) { t2 += rf0[w]; spd += rf1[w]; sp += rf2[w]; }
            t2 *= (1.0f / (float)MPTS);
            out[0] = spd / (sp + EPSF) + t2;
        }
    }
}

extern "C" void kernel_launch(void* const* d_in, const int* in_sizes, int n_in,
                              void* d_out, int out_size)
{
    const float* prob = (const float*)d_in[0];
    const float* gt   = (const float*)d_in[1];
    (void)in_sizes; (void)n_in; (void)out_size;

    chamfer_all<<<NBTOT, TPB>>>(prob, gt, (float*)d_out);
}

// round 9
// speedup vs baseline: 2.9449x; 1.2857x over previous
#include <cuda_runtime.h>
#include <math.h>

// ModifiedChamferLoss: H=W=M=512, N=H*W=262144
// d_in[0]=prob_map [262144] f32, d_in[1]=gt [512,2] f32 (d_in[2] unused; coords from index)
// out: scalar f32
//
// Single launch, 576 blocks x 256 threads.
//  - term1: 512 blocks, one 32(w)x16(h) pixel tile each (2 px/thread), GT candidates
//    pruned by triangle inequality (keep iff d(center,g) <= dmin_center + 2*r_tile).
//  - term2: 64 blocks x 8 warps, one GT per warp. s = 1/(p^4+eps') >= ~1 so any achieved
//    upper bound U restricts winners to d <= U*(1+eps'): scan a 32x16 box, check coverage,
//    exact square-expansion fallback for the ~1% misses.
//  - last block (persistent u64 modular ticket -> replay-safe, no init) reduces and writes.

#define MPTS  512
#define NB1   512                 /* term1 tile blocks               */
#define NB2B  64                  /* term2 blocks (8 warps each)     */
#define NBTOT (NB1 + NB2B)
#define TPB   256
#define FULLM 0xffffffffu

#define EPSF        1e-6f
#define MAXD_F      724.07733f          /* sqrt(512^2+512^2) */
#define MAXD2_F     524288.0f
#define EPS_OVER_MD 1.3810683e-9f       /* 1e-6f / 724.07733f */

typedef unsigned long long ull;

__device__ __forceinline__ ull pk2(float lo, float hi) {
    ull r; asm("mov.b64 %0, {%1, %2};" : "=l"(r) : "f"(lo), "f"(hi)); return r;
}
#define UNPK2(a, b, v) asm("mov.b64 {%0, %1}, %2;" : "=f"(a), "=f"(b) : "l"(v))
__device__ __forceinline__ ull add2(ull a, ull b) {
    ull r; asm("add.rn.f32x2 %0, %1, %2;" : "=l"(r) : "l"(a), "l"(b)); return r;
}
__device__ __forceinline__ ull mul2(ull a, ull b) {
    ull r; asm("mul.rn.f32x2 %0, %1, %2;" : "=l"(r) : "l"(a), "l"(b)); return r;
}
__device__ __forceinline__ ull fma2(ull a, ull b, ull c) {
    ull r; asm("fma.rn.f32x2 %0, %1, %2, %3;" : "=l"(r) : "l"(a), "l"(b), "l"(c)); return r;
}

__device__ float g_part_pd[NB1];   // per-term1-block partial: sum p*min_d   (plain stores)
__device__ float g_part_p[NB1];    // per-term1-block partial: sum p
__device__ int   g_min2[MPTS];     // per-GT min candidate^2 (float bits), plain stores
__device__ ull   g_done;           // persistent ticket; last block via modulo

__global__ void __launch_bounds__(TPB)
chamfer_all(const float* __restrict__ prob, const float* __restrict__ gt,
            float* __restrict__ out)
{
    const int tid  = threadIdx.x;
    const int lane = tid & 31;
    const int wid  = tid >> 5;
    __shared__ unsigned s_last;

    if (blockIdx.x < NB1) {
        // ========== term1: 32(w) x 16(h) tile; triangle-inequality GT pruning ==========
        __shared__ __align__(16) float s_cgy[MPTS + 2];   // negated, compacted
        __shared__ __align__(16) float s_cgx[MPTS + 2];
        __shared__ float s_wred[8];
        __shared__ int   s_wcA[8], s_wcB[8];
        __shared__ float r_pd[8], r_p[8];

        const int b1  = blockIdx.x;
        const int ty0 = (b1 >> 4) << 4;          // 32 tile-rows of 16 px
        const int tx0 = (b1 & 15) << 5;          // 16 tile-cols of 32 px
        const float cy = (float)ty0 + 7.5f, cx = (float)tx0 + 15.5f;

        // phase A: each thread tests 2 GT points. r_tile = sqrt(7.5^2+15.5^2)=17.22
        float2 gA = ((const float2*)gt)[tid];
        float2 gB = ((const float2*)gt)[tid + 256];
        float dyA = cy - gA.x, dxA = cx - gA.y;
        float dyB = cy - gB.x, dxB = cx - gB.y;
        float dcA = sqrtf(fmaf(dyA, dyA, dxA * dxA));
        float dcB = sqrtf(fmaf(dyB, dyB, dxB * dxB));

        float m = fminf(dcA, dcB);
        #pragma unroll
        for (int o = 16; o; o >>= 1) m = fminf(m, __shfl_down_sync(FULLM, m, o));
        if (lane == 0) s_wred[wid] = m;
        __syncthreads();
        float dmin = s_wred[0];
        #pragma unroll
        for (int w = 1; w < 8; ++w) dmin = fminf(dmin, s_wred[w]);
        const float thr = dmin + 34.94f;         // 2*17.22 + 0.5 slack

        bool keepA = dcA <= thr, keepB = dcB <= thr;
        unsigned balA = __ballot_sync(FULLM, keepA);
        unsigned balB = __ballot_sync(FULLM, keepB);
        if (lane == 0) { s_wcA[wid] = __popc(balA); s_wcB[wid] = __popc(balB); }
        __syncthreads();
        int baseA = 0, totA = 0, baseB = 0, totB = 0;
        #pragma unroll
        for (int w = 0; w < 8; ++w) {
            int a = s_wcA[w], b = s_wcB[w];
            totA += a; totB += b;
            if (w < wid) { baseA += a; baseB += b; }
        }
        if (keepA) {
            int pos = baseA + __popc(balA & ((1u << lane) - 1u));
            s_cgy[pos] = -gA.x; s_cgx[pos] = -gA.y;
        }
        if (keepB) {
            int pos = totA + baseB + __popc(balB & ((1u << lane) - 1u));
            s_cgy[pos] = -gB.x; s_cgx[pos] = -gB.y;
        }
        __syncthreads();
        int ncand = totA + totB;
        if (tid == 0 && (ncand & 1)) { s_cgy[ncand] = s_cgy[ncand - 1]; s_cgx[ncand] = s_cgx[ncand - 1]; }
        const int np = (ncand + 1) & ~1;
        __syncthreads();

        // phase B: 2 vertically-aligned pixels (rows +8 apart) share dx^2; 2 GT per step
        const int y0i = ty0 + (tid >> 5), x0i = tx0 + (tid & 31);
        const int i0  = y0i * 512 + x0i;
        const int i1  = i0 + 8 * 512;
        const float p0 = prob[i0], p1 = prob[i1];

        const ull yy0 = pk2((float)y0i, (float)y0i);
        const ull yy1 = pk2((float)(y0i + 8), (float)(y0i + 8));
        const ull xx0 = pk2((float)x0i, (float)x0i);

        float ma0 = 3.4e38f, mb0 = 3.4e38f, ma1 = 3.4e38f, mb1 = 3.4e38f;
        #pragma unroll 2
        for (int j = 0; j < np; j += 2) {
            ull gyv = *(const ull*)&s_cgy[j];
            ull gxv = *(const ull*)&s_cgx[j];
            ull dxv = add2(gxv, xx0);
            ull dxx = mul2(dxv, dxv);
            {
                ull dyv = add2(gyv, yy0);
                ull d2  = fma2(dyv, dyv, dxx);
                float a, b; UNPK2(a, b, d2);
                ma0 = fminf(ma0, a); mb0 = fminf(mb0, b);
            }
            {
                ull dyv = add2(gyv, yy1);
                ull d2  = fma2(dyv, dyv, dxx);
                float a, b; UNPK2(a, b, d2);
                ma1 = fminf(ma1, a); mb1 = fminf(mb1, b);
            }
        }

        float v_pd = p0 * sqrtf(fminf(ma0, mb0)) + p1 * sqrtf(fminf(ma1, mb1));
        float v_p  = p0 + p1;
        #pragma unroll
        for (int o = 16; o; o >>= 1) {
            v_pd += __shfl_down_sync(FULLM, v_pd, o);
            v_p  += __shfl_down_sync(FULLM, v_p,  o);
        }
        if (lane == 0) { r_pd[wid] = v_pd; r_p[wid] = v_p; }
        __syncthreads();
        if (tid == 0) {
            float a = 0.0f, b = 0.0f;
            #pragma unroll
            for (int w = 0; w < 8; ++w) { a += r_pd[w]; b += r_p[w]; }
            g_part_pd[b1] = a;      // plain stores, no init needed
            g_part_p[b1]  = b;
        }
    } else {
        // ========== term2: one GT point per warp, 32(w) x 16(h) seed box ==========
        const int j  = ((blockIdx.x - NB1) << 3) + wid;    // 0..511
        const float gy = __ldg(&gt[2 * j]);
        const float gx = __ldg(&gt[2 * j + 1]);
        const int ry = min(max(__float2int_rn(gy), 0), 511);
        const int rx = min(max(__float2int_rn(gx), 0), 511);
        const int r0 = min(max(ry - 7, 0), 496);           // 16-row box
        const int c0 = min(max(rx - 15, 0), 480);          // 32-col box

        const int   col = c0 + lane;
        const float dxl = (float)col - gx;
        const float dx2 = dxl * dxl;
        float cmin2 = MAXD2_F;
        #pragma unroll 4
        for (int r = r0; r < r0 + 16; ++r) {
            float p   = __ldg(&prob[r * 512 + col]);
            float dyl = (float)r - gy;
            float d2  = fmaf(dyl, dyl, dx2);
            float p2  = p * p;
            float s   = 1.0f / (p2 * p2 + EPS_OVER_MD);
            float cand = fminf((sqrtf(d2) + EPSF) * s, MAXD_F);
            cmin2 = fminf(cmin2, cand * cand);
        }
        cmin2 = __uint_as_float(__reduce_min_sync(FULLM, __float_as_uint(cmin2)));

        // coverage radius; image-edge sides cover everything beyond them
        float top = (r0 > 0)        ? (gy - (float)r0)        : 1e9f;
        float bot = (r0 + 15 < 511) ? ((float)(r0 + 15) - gy) : 1e9f;
        float lef = (c0 > 0)        ? (gx - (float)c0)        : 1e9f;
        float rig = (c0 + 31 < 511) ? ((float)(c0 + 31) - gx) : 1e9f;
        float rcov = fminf(fminf(top, bot), fminf(lef, rig));

        // cand >= d/(1+eps') -> winners lie within U*(1+eps') of the GT.
        if (cmin2 > rcov * rcov * 0.98f) {     // exact fallback (~1% of warps)
            int W   = (int)ceilf(sqrtf(cmin2) * 1.001f) + 1;
            int rr0 = max(0, ry - W), rr1 = min(511, ry + W);
            int cc0 = max(0, rx - W), cc1 = min(511, rx + W);
            for (int r = rr0; r <= rr1; ++r) {
                float dyl = (float)r - gy;
                float dy2 = dyl * dyl;
                for (int c = cc0 + lane; c <= cc1; c += 32) {
                    float p   = prob[r * 512 + c];
                    float dxe = (float)c - gx;
                    float d2  = fmaf(dxe, dxe, dy2);
                    float p2  = p * p;
                    float s   = 1.0f / (p2 * p2 + EPS_OVER_MD);
                    float cand = fminf((sqrtf(d2) + EPSF) * s, MAXD_F);
                    cmin2 = fminf(cmin2, cand * cand);
                }
            }
            cmin2 = __uint_as_float(__reduce_min_sync(FULLM, __float_as_uint(cmin2)));
        }
        if (lane == 0) g_min2[j] = __float_as_int(cmin2);   // plain store
    }

    // ========== fused finalize: last block of THIS launch reduces and writes out ==========
    __syncthreads();
    if (tid == 0) {
        __threadfence();                       // publish stores before the ticket
        ull old = atomicAdd(&g_done, 1ull);
        s_last = ((old % (ull)NBTOT) == (ull)(NBTOT - 1)) ? 1u : 0u;
    }
    __syncthreads();
    if (s_last) {
        __threadfence();                       // acquire all other blocks' stores
        float v0 = sqrtf(__int_as_float(((volatile int*)g_min2)[tid]))
                 + sqrtf(__int_as_float(((volatile int*)g_min2)[tid + 256]));
        float v1 = ((volatile float*)g_part_pd)[tid] + ((volatile float*)g_part_pd)[tid + 256];
        float v2 = ((volatile float*)g_part_p)[tid]  + ((volatile float*)g_part_p)[tid + 256];
        #pragma unroll
        for (int o = 16; o; o >>= 1) {
            v0 += __shfl_down_sync(FULLM, v0, o);
            v1 += __shfl_down_sync(FULLM, v1, o);
            v2 += __shfl_down_sync(FULLM, v2, o);
        }
        __shared__ float rf0[8], rf1[8], rf2[8];
        if (lane == 0) { rf0[wid] = v0; rf1[wid] = v1; rf2[wid] = v2; }
        __syncthreads();
        if (tid == 0) {
            float t2 = 0.0f, spd = 0.0f, sp = 0.0f;
            #pragma unroll
            for (int w = 0; w < 8; ++w) { t2 += rf0[w]; spd += rf1[w]; sp += rf2[w]; }
            t2 *= (1.0f / (float)MPTS);
            out[0] = spd / (sp + EPSF) + t2;
        }
    }
}

extern "C" void kernel_launch(void* const* d_in, const int* in_sizes, int n_in,
                              void* d_out, int out_size)
{
    const float* prob = (const float*)d_in[0];
    const float* gt   = (const float*)d_in[1];
    (void)in_sizes; (void)n_in; (void)out_size;

    chamfer_all<<<NBTOT, TPB>>>(prob, gt, (float*)d_out);
}